// round 1
// baseline (speedup 1.0000x reference)
#include <cuda_runtime.h>

// VelocityLoss: B=512, S=480, F=149, POS=72, VEL=72, VF=5
// Key algebraic facts exploited:
//  - _train_x1 / _train_x2 never affect the loss (index-0 velocity is sliced away).
//  - mean_p cancels in the velocity difference: vel = (pos[s]-pos[s-1])*std_p.
//  - W_MAT is a fixed sparse scatter: joint j -> part c_part[j] with weight c_w[j].

namespace {
constexpr int B_ = 512;
constexpr int S_ = 480;
constexpr int F_ = 149;
constexpr int VF_ = 5;
constexpr int SPW = 8;   // sequence rows per block (one per warp, 256 threads)
}

__device__ double g_acc[3];   // [0]=A (vel mse sum), [1]=B0 (s==0 pred^2 sum), [2]=C (factor mse sum)

// weight_j / wsum(part_j), parts per joint (from reference _WEIGHT/_PARTS)
__constant__ float c_w[24] = {
    0.1f, 0.2f, 0.3f, 0.4f,            // part 1 (wsum 10)
    0.1f, 0.2f, 0.3f, 0.4f,            // part 2 (wsum 10)
    1.f/9.f, 1.f/9.f, 1.f/9.f, 1.f/9.f, 1.f/9.f,  // part 0 (wsum 9)
    0.1f, 0.2f, 0.3f, 0.4f,            // part 3
    0.1f, 0.2f, 0.3f, 0.4f,            // part 4
    1.f/9.f, 2.f/9.f, 1.f/9.f          // part 0
};
__constant__ int c_part[24] = {1,1,1,1, 2,2,2,2, 0,0,0,0,0, 3,3,3,3, 4,4,4,4, 0,0,0};

__global__ void __launch_bounds__(32) init_acc() {
    if (threadIdx.x < 3) g_acc[threadIdx.x] = 0.0;
}

__global__ void __launch_bounds__(256) vel_loss_main(
    const float* __restrict__ pred,   // (B, S, F)
    const float* __restrict__ tvft,   // (B, S+1, VF)
    const float* __restrict__ meanv,  // (F,)
    const float* __restrict__ stdv)   // (F,)
{
    __shared__ float s_stdp[72], s_meanv[72], s_rstdv[72];
    __shared__ float s_meanf[8], s_rstdf[8];
    __shared__ double s_part[SPW][3];

    const int tid = threadIdx.x;
    if (tid < 72) {
        s_stdp[tid]  = stdv[tid];
        s_meanv[tid] = meanv[72 + tid];
        s_rstdv[tid] = 1.0f / stdv[72 + tid];
    }
    if (tid < VF_) {
        s_meanf[tid] = meanv[144 + tid];
        s_rstdf[tid] = 1.0f / stdv[144 + tid];
    }
    __syncthreads();

    const int warp = tid >> 5;
    const int lane = tid & 31;
    const int b = blockIdx.x / (S_ / SPW);
    const int s = (blockIdx.x % (S_ / SPW)) * SPW + warp;

    float accA = 0.f, accB = 0.f, accC = 0.f;
    float f0 = 0.f, f1 = 0.f, f2 = 0.f, f3 = 0.f, f4 = 0.f;

    const float* row = pred + ((size_t)b * S_ + s) * F_;

    if (lane < 24) {
        const int j = lane * 3;
        const float pv0 = row[77 + j], pv1 = row[78 + j], pv2 = row[79 + j];
        if (s == 0) {
            // only the zero-target MSE on pred_vel[:,0]
            accB = pv0 * pv0 + pv1 * pv1 + pv2 * pv2;
        } else {
            const float* prow = row - F_;
            const float v0 = (row[j + 0] - prow[j + 0]) * s_stdp[j + 0];
            const float v1 = (row[j + 1] - prow[j + 1]) * s_stdp[j + 1];
            const float v2 = (row[j + 2] - prow[j + 2]) * s_stdp[j + 2];
            const float d0 = pv0 - (v0 - s_meanv[j + 0]) * s_rstdv[j + 0];
            const float d1 = pv1 - (v1 - s_meanv[j + 1]) * s_rstdv[j + 1];
            const float d2 = pv2 - (v2 - s_meanv[j + 2]) * s_rstdv[j + 2];
            accA = d0 * d0 + d1 * d1 + d2 * d2;

            const float nrm = sqrtf(v0 * v0 + v1 * v1 + v2 * v2);
            const float contrib = nrm * c_w[lane];
            const int p = c_part[lane];
            f0 = (p == 0) ? contrib : 0.f;
            f1 = (p == 1) ? contrib : 0.f;
            f2 = (p == 2) ? contrib : 0.f;
            f3 = (p == 3) ? contrib : 0.f;
            f4 = (p == 4) ? contrib : 0.f;
        }
    }

    // full-warp butterfly reduction (inactive lanes hold zeros)
    #pragma unroll
    for (int off = 16; off; off >>= 1) {
        accA += __shfl_xor_sync(0xffffffffu, accA, off);
        accB += __shfl_xor_sync(0xffffffffu, accB, off);
        f0   += __shfl_xor_sync(0xffffffffu, f0, off);
        f1   += __shfl_xor_sync(0xffffffffu, f1, off);
        f2   += __shfl_xor_sync(0xffffffffu, f2, off);
        f3   += __shfl_xor_sync(0xffffffffu, f3, off);
        f4   += __shfl_xor_sync(0xffffffffu, f4, off);
    }

    if (lane == 0) {
        if (s > 0) {
            const float* tr = tvft + ((size_t)b * (S_ + 1) + s) * VF_;
            float fp[5] = {f0, f1, f2, f3, f4};
            #pragma unroll
            for (int p = 0; p < VF_; p++) {
                const float d = tr[p] - (fp[p] - s_meanf[p]) * s_rstdf[p];
                accC += d * d;
            }
        }
        s_part[warp][0] = (double)accA;
        s_part[warp][1] = (double)accB;
        s_part[warp][2] = (double)accC;
    }
    __syncthreads();

    if (warp == 0) {
        double a = (lane < SPW) ? s_part[lane][0] : 0.0;
        double bb = (lane < SPW) ? s_part[lane][1] : 0.0;
        double c = (lane < SPW) ? s_part[lane][2] : 0.0;
        #pragma unroll
        for (int off = 4; off; off >>= 1) {
            a  += __shfl_xor_sync(0xffffffffu, a, off);
            bb += __shfl_xor_sync(0xffffffffu, bb, off);
            c  += __shfl_xor_sync(0xffffffffu, c, off);
        }
        if (lane == 0) {
            atomicAdd(&g_acc[0], a);
            atomicAdd(&g_acc[1], bb);
            atomicAdd(&g_acc[2], c);
        }
    }
}

__global__ void __launch_bounds__(32) finalize_loss(float* __restrict__ out) {
    if (threadIdx.x == 0) {
        const double nA = (double)B_ * (double)(S_ - 1) * 72.0;
        const double nB = (double)B_ * 72.0;
        const double nC = (double)B_ * (double)(S_ - 1) * (double)VF_;
        const double loss1 = 10.0 * g_acc[0] / nA + 20.0 * g_acc[1] / nB;
        const double loss2 = 10.0 * g_acc[2] / nC;
        out[0] = (float)(2.0 * loss1 + 1.5 * loss2);
    }
}

extern "C" void kernel_launch(void* const* d_in, const int* in_sizes, int n_in,
                              void* d_out, int out_size) {
    const float* pred = (const float*)d_in[0];   // predict_seq (B,S,F)
    // d_in[1] = _train_x1 (unused: index-0 velocity is sliced out of both losses)
    // d_in[2] = _train_x2 (unused by reference)
    const float* tvft = (const float*)d_in[3];   // _true_vel_factor (B,S+1,VF)
    const float* mean = (const float*)d_in[4];   // _mean (F,)
    const float* stdv = (const float*)d_in[5];   // _std (F,)

    init_acc<<<1, 32>>>();
    vel_loss_main<<<B_ * (S_ / SPW), 256>>>(pred, tvft, mean, stdv);
    finalize_loss<<<1, 32>>>((float*)d_out);
}

// round 2
// speedup vs baseline: 2.2984x; 2.2984x over previous
#include <cuda_runtime.h>

// VelocityLoss on GB300.
// Algebraic reductions: _train_x1/_train_x2 unused (index-0 velocity sliced out);
// mean_p cancels in the velocity diff; W_MAT is a fixed sparse joint->part scatter.
//
// Layout: one warp owns a chunk of CH=30 consecutive sequence rows of one batch.
// Lanes 0..23 each own one joint (3 floats), with lane->joint remapped so the
// 5 body parts are shuffle-aligned groups:
//   lanes 0-7  -> part0 joints {8,9,10,11,12,21,22,23}
//   lanes 8-11 -> part1 {0..3}, 12-15 -> part2 {4..7},
//   lanes16-19 -> part3 {13..16}, 20-23 -> part4 {17..20}
// Per row only 3 shuffles (xor 1,2,4) produce all part sums.
// Prev-row positions live in registers (each element loaded exactly once).
// Single kernel launch; last block (ticket) finalizes + resets accumulators.

namespace {
constexpr int B_ = 512;
constexpr int S_ = 480;
constexpr int F_ = 149;
constexpr int VF_ = 5;
constexpr int CH = 30;                    // rows per warp chunk
constexpr int CPB = S_ / CH;              // 16 chunks per batch row
constexpr int WPB = 8;                    // warps per block
constexpr int NBLK = B_ * CPB / WPB;      // 1024 blocks
}

__device__ double g_acc[3] = {0.0, 0.0, 0.0};
__device__ unsigned int g_ticket = 0;

// lane -> joint (remapped for aligned part groups)
__constant__ int c_j[24] = {
    8, 9, 10, 11, 12, 21, 22, 23,    // part0
    0, 1, 2, 3,                      // part1
    4, 5, 6, 7,                      // part2
    13, 14, 15, 16,                  // part3
    17, 18, 19, 20                   // part4
};
// lane -> weight / wsum(part)
__constant__ float c_wl[24] = {
    1.f/9, 1.f/9, 1.f/9, 1.f/9, 1.f/9, 1.f/9, 2.f/9, 1.f/9,
    0.1f, 0.2f, 0.3f, 0.4f,
    0.1f, 0.2f, 0.3f, 0.4f,
    0.1f, 0.2f, 0.3f, 0.4f,
    0.1f, 0.2f, 0.3f, 0.4f
};

__global__ void __launch_bounds__(256) vel_loss_fused(
    const float* __restrict__ pred,   // (B, S, F)
    const float* __restrict__ tvft,   // (B, S+1, VF)
    const float* __restrict__ meanv,  // (F,)
    const float* __restrict__ stdv,   // (F,)
    float* __restrict__ out)
{
    const int tid  = threadIdx.x;
    const int lane = tid & 31;
    const int warp = tid >> 5;
    const int idx  = blockIdx.x * WPB + warp;   // chunk id in [0, 8192)
    const int b    = idx / CPB;
    const int s0   = (idx % CPB) * CH;

    // per-lane joint parameters (loaded once)
    int jj = 0; float w = 0.f;
    float sp0 = 0, sp1 = 0, sp2 = 0;
    float mv0 = 0, mv1 = 0, mv2 = 0;
    float rv0 = 0, rv1 = 0, rv2 = 0;
    if (lane < 24) {
        jj = c_j[lane] * 3;
        w  = c_wl[lane];
        sp0 = stdv[jj];     sp1 = stdv[jj + 1];     sp2 = stdv[jj + 2];
        mv0 = meanv[72+jj]; mv1 = meanv[72+jj+1];   mv2 = meanv[72+jj+2];
        rv0 = 1.0f / stdv[72+jj];
        rv1 = 1.0f / stdv[72+jj+1];
        rv2 = 1.0f / stdv[72+jj+2];
    }

    // factor-reduce lanes: lane 0 -> part0, 8->1, 12->2, 16->3, 20->4
    int pidx = -1;
    if (lane == 0) pidx = 0;
    else if (lane == 8)  pidx = 1;
    else if (lane == 12) pidx = 2;
    else if (lane == 16) pidx = 3;
    else if (lane == 20) pidx = 4;
    float mf = 0.f, rf = 0.f;
    if (pidx >= 0) {
        mf = meanv[144 + pidx];
        rf = 1.0f / stdv[144 + pidx];
    }

    float accA = 0.f, accB = 0.f, accC = 0.f;

    const float* rowbase = pred + ((size_t)(b * S_ + s0)) * F_;
    const float* trbase  = tvft + ((size_t)b * (S_ + 1)) * VF_;

    // previous-row positions in registers
    float p0 = 0.f, p1 = 0.f, p2 = 0.f;
    int sBeg = s0;
    if (s0 == 0) {
        if (lane < 24) {
            p0 = rowbase[jj]; p1 = rowbase[jj + 1]; p2 = rowbase[jj + 2];
            const float q0 = rowbase[77 + jj];
            const float q1 = rowbase[78 + jj];
            const float q2 = rowbase[79 + jj];
            accB = q0 * q0 + q1 * q1 + q2 * q2;   // s==0: zero-target term only
        }
        sBeg = 1;
    } else {
        if (lane < 24) {
            const float* rp = rowbase - F_;
            p0 = rp[jj]; p1 = rp[jj + 1]; p2 = rp[jj + 2];
        }
    }

    const int sEnd = s0 + CH;
    #pragma unroll 2
    for (int s = sBeg; s < sEnd; ++s) {
        const float* r = pred + ((size_t)(b * S_ + s)) * F_;
        float contrib = 0.f;
        if (lane < 24) {
            const float c0 = r[jj], c1 = r[jj + 1], c2 = r[jj + 2];
            const float q0 = r[77 + jj], q1 = r[78 + jj], q2 = r[79 + jj];
            const float v0 = (c0 - p0) * sp0;
            const float v1 = (c1 - p1) * sp1;
            const float v2 = (c2 - p2) * sp2;
            const float d0 = q0 - (v0 - mv0) * rv0;
            const float d1 = q1 - (v1 - mv1) * rv1;
            const float d2 = q2 - (v2 - mv2) * rv2;
            accA += d0 * d0 + d1 * d1 + d2 * d2;
            contrib = sqrtf(v0 * v0 + v1 * v1 + v2 * v2) * w;
            p0 = c0; p1 = c1; p2 = c2;
        }
        // aligned group sums: 3 shuffles total
        float g4 = contrib;
        g4 += __shfl_xor_sync(0xffffffffu, g4, 1);
        g4 += __shfl_xor_sync(0xffffffffu, g4, 2);
        const float g8 = g4 + __shfl_xor_sync(0xffffffffu, g4, 4);
        if (pidx >= 0) {
            const float f = (pidx == 0) ? g8 : g4;
            const float d = trbase[(size_t)s * VF_ + pidx] - (f - mf) * rf;
            accC += d * d;
        }
    }

    // warp reduction (once per chunk)
    #pragma unroll
    for (int off = 16; off; off >>= 1) {
        accA += __shfl_xor_sync(0xffffffffu, accA, off);
        accB += __shfl_xor_sync(0xffffffffu, accB, off);
        accC += __shfl_xor_sync(0xffffffffu, accC, off);
    }

    __shared__ double sA[WPB], sB[WPB], sC[WPB];
    if (lane == 0) {
        sA[warp] = (double)accA;
        sB[warp] = (double)accB;
        sC[warp] = (double)accC;
    }
    __syncthreads();

    if (warp == 0) {
        double a  = (lane < WPB) ? sA[lane] : 0.0;
        double bb = (lane < WPB) ? sB[lane] : 0.0;
        double c  = (lane < WPB) ? sC[lane] : 0.0;
        #pragma unroll
        for (int off = 4; off; off >>= 1) {
            a  += __shfl_xor_sync(0xffffffffu, a, off);
            bb += __shfl_xor_sync(0xffffffffu, bb, off);
            c  += __shfl_xor_sync(0xffffffffu, c, off);
        }
        if (lane == 0) {
            atomicAdd(&g_acc[0], a);
            atomicAdd(&g_acc[1], bb);
            atomicAdd(&g_acc[2], c);
            __threadfence();
            const unsigned t = atomicAdd(&g_ticket, 1u);
            if (t == (unsigned)(NBLK - 1)) {
                // all other blocks' adds are ordered before their ticket inc
                __threadfence();
                volatile double* ga = g_acc;
                const double A  = ga[0];
                const double B0 = ga[1];
                const double C  = ga[2];
                const double nA = (double)B_ * (double)(S_ - 1) * 72.0;
                const double nB = (double)B_ * 72.0;
                const double nC = (double)B_ * (double)(S_ - 1) * (double)VF_;
                const double loss1 = 10.0 * A / nA + 20.0 * B0 / nB;
                const double loss2 = 10.0 * C / nC;
                out[0] = (float)(2.0 * loss1 + 1.5 * loss2);
                // reset for the next graph replay
                ga[0] = 0.0; ga[1] = 0.0; ga[2] = 0.0;
                g_ticket = 0;
            }
        }
    }
}

extern "C" void kernel_launch(void* const* d_in, const int* in_sizes, int n_in,
                              void* d_out, int out_size) {
    const float* pred = (const float*)d_in[0];   // predict_seq (B,S,F)
    // d_in[1] = _train_x1 (unused), d_in[2] = _train_x2 (unused)
    const float* tvft = (const float*)d_in[3];   // _true_vel_factor (B,S+1,VF)
    const float* mean = (const float*)d_in[4];   // _mean (F,)
    const float* stdv = (const float*)d_in[5];   // _std (F,)

    vel_loss_fused<<<NBLK, 256>>>(pred, tvft, mean, stdv, (float*)d_out);
}